// round 13
// baseline (speedup 1.0000x reference)
#include <cuda_runtime.h>
#include <math_constants.h>

#define N_IN   16384
#define NCONV  128
#define KMAX   11
#define TPB    256
#define CPB    16    // convs per block (processed block-cooperatively)
#define CHUNK  65    // 65 == 1 (mod 32) -> conflict-free lanes for any dilation

union pk2 { unsigned long long u; float2 f; };

__device__ __forceinline__ unsigned long long fma2(
    unsigned long long a, unsigned long long b, unsigned long long c)
{
    unsigned long long r;
    asm("fma.rn.f32x2 %0, %1, %2, %3;" : "=l"(r) : "l"(a), "l"(b), "l"(c));
    return r;
}

__device__ __forceinline__ float warpReduceMax(float v) {
#pragma unroll
    for (int o = 16; o > 0; o >>= 1)
        v = fmaxf(v, __shfl_xor_sync(0xffffffffu, v, o));
    return v;
}
__device__ __forceinline__ int warpReduceSum(int v) {
#pragma unroll
    for (int o = 16; o > 0; o >>= 1)
        v += __shfl_xor_sync(0xffffffffu, v, o);
    return v;
}

__device__ __forceinline__ int meta_at(const void* arr, int c, bool is64) {
    if (is64) return (int)((const long long*)arr)[c];
    return ((const int*)arr)[c];
}

// ======== packed dual-stream ring (2 outputs per iteration, FFMA2) ========
// Stream A: outputs [m0, m0+h), taps from i0;  Stream B: [m0+h, m0+2h),
// taps from i0 + h*d. Window Z[t] = (tapA, tapB) packed. h >= K required.
template <int K>
__device__ __forceinline__ void ring2_fast(
    const float* __restrict__ xs, const pk2* __restrict__ WP,
    unsigned long long bias2,
    int i0, int d, int h,
    float& mx0, float& mx1, int& neg)
{
    const float* pA = xs + i0;
    const float* pB = pA + h * d;
    pk2 Z[K];
#pragma unroll
    for (int s = 0; s < K - 1; s++) {
        Z[s].f.x = *pA; pA += d;
        Z[s].f.y = *pB; pB += d;
    }

    const int full = h / K;
    const int rem  = h - full * K;

    for (int g = 0; g < full; g++) {
#pragma unroll
        for (int s = 0; s < K; s++) {
            Z[(s + K - 1) % K].f.x = *pA; pA += d;
            Z[(s + K - 1) % K].f.y = *pB; pB += d;
            unsigned long long Y = fma2(WP[0].u, Z[s % K].u, bias2);
#pragma unroll
            for (int t = 1; t < K; t++)
                Y = fma2(WP[t].u, Z[(s + t) % K].u, Y);
            pk2 y; y.u = Y;
            mx0 = fmaxf(mx0, y.f.x);
            mx1 = fmaxf(mx1, y.f.y);
            neg += (int)(__float_as_uint(y.f.x) >> 31);
            neg += (int)(__float_as_uint(y.f.y) >> 31);
        }
    }
    if (rem) {
#pragma unroll
        for (int s = 0; s < K; s++) {
            if (s < rem) {
                Z[(s + K - 1) % K].f.x = *pA; pA += d;
                Z[(s + K - 1) % K].f.y = *pB; pB += d;
                unsigned long long Y = fma2(WP[0].u, Z[s % K].u, bias2);
#pragma unroll
                for (int t = 1; t < K; t++)
                    Y = fma2(WP[t].u, Z[(s + t) % K].u, Y);
                pk2 y; y.u = Y;
                mx0 = fmaxf(mx0, y.f.x);
                mx1 = fmaxf(mx1, y.f.y);
                neg += (int)(__float_as_uint(y.f.x) >> 31);
                neg += (int)(__float_as_uint(y.f.y) >> 31);
            }
        }
    }
}

template <int K>
__device__ __forceinline__ void ring2_clamped(
    const float* __restrict__ xs, const pk2* __restrict__ WP,
    unsigned long long bias2,
    int i0, int d, int h,
    float& mx0, float& mx1, int& neg)
{
    int ixA = i0;
    int ixB = i0 + h * d;
    pk2 Z[K];
#pragma unroll
    for (int s = 0; s < K - 1; s++) {
        Z[s].f.x = xs[min((unsigned)ixA, (unsigned)N_IN)]; ixA += d;
        Z[s].f.y = xs[min((unsigned)ixB, (unsigned)N_IN)]; ixB += d;
    }

    const int full = h / K;
    const int rem  = h - full * K;

    for (int g = 0; g < full; g++) {
#pragma unroll
        for (int s = 0; s < K; s++) {
            Z[(s + K - 1) % K].f.x = xs[min((unsigned)ixA, (unsigned)N_IN)]; ixA += d;
            Z[(s + K - 1) % K].f.y = xs[min((unsigned)ixB, (unsigned)N_IN)]; ixB += d;
            unsigned long long Y = fma2(WP[0].u, Z[s % K].u, bias2);
#pragma unroll
            for (int t = 1; t < K; t++)
                Y = fma2(WP[t].u, Z[(s + t) % K].u, Y);
            pk2 y; y.u = Y;
            mx0 = fmaxf(mx0, y.f.x);
            mx1 = fmaxf(mx1, y.f.y);
            neg += (int)(__float_as_uint(y.f.x) >> 31);
            neg += (int)(__float_as_uint(y.f.y) >> 31);
        }
    }
    if (rem) {
#pragma unroll
        for (int s = 0; s < K; s++) {
            if (s < rem) {
                Z[(s + K - 1) % K].f.x = xs[min((unsigned)ixA, (unsigned)N_IN)]; ixA += d;
                Z[(s + K - 1) % K].f.y = xs[min((unsigned)ixB, (unsigned)N_IN)]; ixB += d;
                unsigned long long Y = fma2(WP[0].u, Z[s % K].u, bias2);
#pragma unroll
                for (int t = 1; t < K; t++)
                    Y = fma2(WP[t].u, Z[(s + t) % K].u, Y);
                pk2 y; y.u = Y;
                mx0 = fmaxf(mx0, y.f.x);
                mx1 = fmaxf(mx1, y.f.y);
                neg += (int)(__float_as_uint(y.f.x) >> 31);
                neg += (int)(__float_as_uint(y.f.y) >> 31);
            }
        }
    }
}

// ======== scalar ring (R8-proven) for short chunks ========
template <int K>
__device__ __forceinline__ void ring_fast(
    const float* __restrict__ xs, const pk2* __restrict__ WP, float bias,
    int i0, int d, int len, float& mx, int& neg)
{
    const float* ptr = xs + i0;
    float z[K];
#pragma unroll
    for (int s = 0; s < K - 1; s++) { z[s] = *ptr; ptr += d; }

    const int full = len / K;
    const int rem  = len - full * K;

    for (int g = 0; g < full; g++) {
#pragma unroll
        for (int s = 0; s < K; s++) {
            z[(s + K - 1) % K] = *ptr; ptr += d;
            float y = fmaf(WP[0].f.x, z[s % K], bias);
#pragma unroll
            for (int t = 1; t < K; t++)
                y = fmaf(WP[t].f.x, z[(s + t) % K], y);
            mx = fmaxf(mx, y);
            neg += (int)(__float_as_uint(y) >> 31);
        }
    }
    if (rem) {
#pragma unroll
        for (int s = 0; s < K; s++) {
            if (s < rem) {
                z[(s + K - 1) % K] = *ptr; ptr += d;
                float y = fmaf(WP[0].f.x, z[s % K], bias);
#pragma unroll
                for (int t = 1; t < K; t++)
                    y = fmaf(WP[t].f.x, z[(s + t) % K], y);
                mx = fmaxf(mx, y);
                neg += (int)(__float_as_uint(y) >> 31);
            }
        }
    }
}

template <int K>
__device__ __forceinline__ void ring_clamped(
    const float* __restrict__ xs, const pk2* __restrict__ WP, float bias,
    int i0, int d, int len, float& mx, int& neg)
{
    int ix = i0;
    float z[K];
#pragma unroll
    for (int s = 0; s < K - 1; s++) {
        z[s] = xs[min((unsigned)ix, (unsigned)N_IN)]; ix += d;
    }

    const int full = len / K;
    const int rem  = len - full * K;

    for (int g = 0; g < full; g++) {
#pragma unroll
        for (int s = 0; s < K; s++) {
            z[(s + K - 1) % K] = xs[min((unsigned)ix, (unsigned)N_IN)]; ix += d;
            float y = fmaf(WP[0].f.x, z[s % K], bias);
#pragma unroll
            for (int t = 1; t < K; t++)
                y = fmaf(WP[t].f.x, z[(s + t) % K], y);
            mx = fmaxf(mx, y);
            neg += (int)(__float_as_uint(y) >> 31);
        }
    }
    if (rem) {
#pragma unroll
        for (int s = 0; s < K; s++) {
            if (s < rem) {
                z[(s + K - 1) % K] = xs[min((unsigned)ix, (unsigned)N_IN)]; ix += d;
                float y = fmaf(WP[0].f.x, z[s % K], bias);
#pragma unroll
                for (int t = 1; t < K; t++)
                    y = fmaf(WP[t].f.x, z[(s + t) % K], y);
                mx = fmaxf(mx, y);
                neg += (int)(__float_as_uint(y) >> 31);
            }
        }
    }
}

// Dispatch one chunk of len outputs starting at tap index i0 (= r + m0*d).
template <int K>
__device__ __forceinline__ void process_chunk(
    const float* __restrict__ xs, const pk2* __restrict__ WP,
    unsigned long long bias2,
    int i0, int d, int len,
    float& mx0, float& mx1, int& neg)
{
    const bool fast = (i0 >= 0) && (i0 + (len + K - 2) * d < N_IN);
    if (len >= 2 * K) {
        const int h = len >> 1;
        if (fast) ring2_fast<K>(xs, WP, bias2, i0, d, h, mx0, mx1, neg);
        else      ring2_clamped<K>(xs, WP, bias2, i0, d, h, mx0, mx1, neg);
        if (len & 1) {
            // leftover last output, scalar clamped gather
            int ix = i0 + (len - 1) * d;
            float y = ((pk2*)&bias2)->f.x;
#pragma unroll
            for (int t = 0; t < K; t++) {
                y = fmaf(WP[t].f.x, xs[min((unsigned)(ix), (unsigned)N_IN)], y);
                ix += d;
            }
            mx0 = fmaxf(mx0, y);
            neg += (int)(__float_as_uint(y) >> 31);
        }
    } else {
        if (fast) ring_fast<K>(xs, WP, ((pk2*)&bias2)->f.x, i0, d, len, mx0, neg);
        else      ring_clamped<K>(xs, WP, ((pk2*)&bias2)->f.x, i0, d, len, mx0, neg);
    }
}

// Whole block cooperates on one conv. Outputs u = t - p = r + m*d.
template <int K>
__device__ __forceinline__ void conv_feat_block(
    const float* __restrict__ xs,
    const float* __restrict__ wrow, float bias,
    int d, int p, int L,
    float& mx_out, int& neg_out)
{
    pk2 WP[K];
#pragma unroll
    for (int j = 0; j < K; j++) { float wj = wrow[j]; WP[j].f.x = wj; WP[j].f.y = wj; }
    pk2 b2; b2.f.x = bias; b2.f.y = bias;
    const unsigned long long bias2 = b2.u;

    float mx0 = -CUDART_INF_F, mx1 = -CUDART_INF_F;
    int   neg = 0;
    const int tid = threadIdx.x;

    // Hoisted divides: m_lo(r) = -(pq + (prm+r >= d)); m_hi(r) = aq - (r > arm)
    const int A   = L - 1 - p;
    const int pq  = p / d, prm = p - pq * d;
    const int aq  = A / d, arm = A - aq * d;

    if (d >= TPB) {
        // phase per thread, full phase in one chunk
        for (int r = tid; r < d; r += TPB) {
            const int m_lo = -(pq + ((prm + r) >= d ? 1 : 0));
            const int m_hi = aq - (r > arm ? 1 : 0);
            const int len  = m_hi - m_lo + 1;
            if (len <= 0) continue;
            process_chunk<K>(xs, WP, bias2, r + m_lo * d, d, len, mx0, mx1, neg);
        }
    } else {
        const int maxlen = (L + d - 1) / d;
        const int nQ     = (maxlen + CHUNK - 1) / CHUNK;
        const int nItems = d * nQ;
        const float rd   = 1.0f / (float)d;

        for (int j = tid; j < nItems; j += TPB) {
            // q = j / d, r = j % d via float reciprocal (+/-1 fixup)
            int q = (int)((float)j * rd);
            int r = j - q * d;
            if (r < 0)       { r += d; q--; }
            else if (r >= d) { r -= d; q++; }

            const int m_lo = -(pq + ((prm + r) >= d ? 1 : 0));
            const int m_hi = aq - (r > arm ? 1 : 0);
            const int m0   = m_lo + q * CHUNK;
            const int m1   = min(m0 + CHUNK, m_hi + 1);
            const int len  = m1 - m0;
            if (len <= 0) continue;
            process_chunk<K>(xs, WP, bias2, r + m0 * d, d, len, mx0, mx1, neg);
        }
    }

    mx_out = fmaxf(mx0, mx1);
    neg_out = neg;
}

__global__ void __launch_bounds__(TPB, 3)
feat_kernel(const float* __restrict__ x,
            const float* __restrict__ W,
            const float* __restrict__ B,
            const void* __restrict__ KS,
            const void* __restrict__ DS,
            const void* __restrict__ PS,
            float* __restrict__ out)
{
    extern __shared__ float xs[];   // N_IN + zero sentinel
    const int b = blockIdx.y;

    {
        const float4* xr4 = (const float4*)(x + (size_t)b * N_IN);
        float4* xs4 = (float4*)xs;
        for (int i = threadIdx.x; i < N_IN / 4; i += TPB)
            xs4[i] = xr4[i];
        if (threadIdx.x == 0) xs[N_IN] = 0.0f;
    }

    __shared__ float rmax[TPB / 32];
    __shared__ int   rneg[TPB / 32];
    __syncthreads();

    // int64 vs int32 metadata: kernel_sizes[0] in {7,9,11}; for int64 the
    // second 32-bit word is 0, for int32 it's kernel_sizes[1] (>=7).
    const bool is64 = (((const int*)KS)[1] == 0);

    const int c0 = blockIdx.x * CPB;
    for (int c = c0; c < c0 + CPB; ++c) {
        const int k = meta_at(KS, c, is64);
        const int d = meta_at(DS, c, is64);
        const int p = meta_at(PS, c, is64);
        const int L = N_IN + 2 * p - d * (k - 1);

        const float* wrow = W + c * KMAX;
        const float bias  = B[c];

        float mx; int neg;
        if (k == 7)       conv_feat_block<7 >(xs, wrow, bias, d, p, L, mx, neg);
        else if (k == 9)  conv_feat_block<9 >(xs, wrow, bias, d, p, L, mx, neg);
        else              conv_feat_block<11>(xs, wrow, bias, d, p, L, mx, neg);

        mx  = warpReduceMax(mx);
        neg = warpReduceSum(neg);
        const int warp = threadIdx.x >> 5;
        const int lane = threadIdx.x & 31;
        if (lane == 0) { rmax[warp] = mx; rneg[warp] = neg; }
        __syncthreads();
        if (threadIdx.x == 0) {
            float m = rmax[0]; int n = rneg[0];
#pragma unroll
            for (int i = 1; i < TPB / 32; i++) {
                m = fmaxf(m, rmax[i]);
                n += rneg[i];
            }
            const size_t base = (size_t)b * (2 * NCONV) + 2 * c;
            out[base]     = m;
            out[base + 1] = (float)(L - n) / (float)L;
        }
        __syncthreads();
    }
}

extern "C" void kernel_launch(void* const* d_in, const int* in_sizes, int n_in,
                              void* d_out, int out_size)
{
    const float* x  = (const float*)d_in[0];
    const float* W  = (const float*)d_in[1];
    const float* B  = (const float*)d_in[2];
    const void*  KS = d_in[3];
    const void*  DS = d_in[4];
    const void*  PS = d_in[5];
    float* out = (float*)d_out;

    const int batch = in_sizes[0] / N_IN;   // 256

    const size_t smem = (N_IN + 16) * sizeof(float);
    cudaFuncSetAttribute(feat_kernel,
                         cudaFuncAttributeMaxDynamicSharedMemorySize,
                         (int)smem);

    dim3 grid(NCONV / CPB, batch);
    feat_kernel<<<grid, TPB, smem>>>(x, W, B, KS, DS, PS, out);
}

// round 14
// speedup vs baseline: 1.1855x; 1.1855x over previous
#include <cuda_runtime.h>
#include <math_constants.h>

#define N_IN   16384
#define NCONV  128
#define KMAX   11
#define TPB    512
#define CPB    16    // convs per block (processed block-cooperatively)
#define CHUNK  33    // 33 == 1 (mod 32) -> conflict-free lanes for any dilation

__device__ __forceinline__ float warpReduceMax(float v) {
#pragma unroll
    for (int o = 16; o > 0; o >>= 1)
        v = fmaxf(v, __shfl_xor_sync(0xffffffffu, v, o));
    return v;
}
__device__ __forceinline__ int warpReduceSum(int v) {
#pragma unroll
    for (int o = 16; o > 0; o >>= 1)
        v += __shfl_xor_sync(0xffffffffu, v, o);
    return v;
}

__device__ __forceinline__ int meta_at(const void* arr, int c, bool is64) {
    if (is64) return (int)((const long long*)arr)[c];
    return ((const int*)arr)[c];
}

// ---- ring FIR, no bounds checks. Loads exactly len+K-1 taps:
// preload K-1, then load-one/compute-one. Max address: i0+(len+K-2)*d. ----
template <int K>
__device__ __forceinline__ void ring_fast(
    const float* __restrict__ xs, const float* __restrict__ w, float bias,
    int i0, int d, int len, float& mx, int& neg)
{
    const float* ptr = xs + i0;
    float z[K];
#pragma unroll
    for (int s = 0; s < K - 1; s++) { z[s] = *ptr; ptr += d; }

    const int full = len / K;
    const int rem  = len - full * K;

    for (int g = 0; g < full; g++) {
#pragma unroll
        for (int s = 0; s < K; s++) {
            z[(s + K - 1) % K] = *ptr; ptr += d;   // newest tap
            float y = fmaf(w[0], z[s % K], bias);
#pragma unroll
            for (int t = 1; t < K; t++)
                y = fmaf(w[t], z[(s + t) % K], y);
            mx = fmaxf(mx, y);
            neg += (int)(__float_as_uint(y) >> 31);
        }
    }
    if (rem) {
#pragma unroll
        for (int s = 0; s < K; s++) {
            if (s < rem) {
                z[(s + K - 1) % K] = *ptr; ptr += d;
                float y = fmaf(w[0], z[s % K], bias);
#pragma unroll
                for (int t = 1; t < K; t++)
                    y = fmaf(w[t], z[(s + t) % K], y);
                mx = fmaxf(mx, y);
                neg += (int)(__float_as_uint(y) >> 31);
            }
        }
    }
}

// ---- same ring, OOB taps clamped to zero sentinel xs[N_IN] (edge chunks) ----
template <int K>
__device__ __forceinline__ void ring_clamped(
    const float* __restrict__ xs, const float* __restrict__ w, float bias,
    int i0, int d, int len, float& mx, int& neg)
{
    int ix = i0;
    float z[K];
#pragma unroll
    for (int s = 0; s < K - 1; s++) {
        unsigned ui = min((unsigned)ix, (unsigned)N_IN);
        z[s] = xs[ui]; ix += d;
    }

    const int full = len / K;
    const int rem  = len - full * K;

    for (int g = 0; g < full; g++) {
#pragma unroll
        for (int s = 0; s < K; s++) {
            unsigned ui = min((unsigned)ix, (unsigned)N_IN);
            z[(s + K - 1) % K] = xs[ui]; ix += d;
            float y = fmaf(w[0], z[s % K], bias);
#pragma unroll
            for (int t = 1; t < K; t++)
                y = fmaf(w[t], z[(s + t) % K], y);
            mx = fmaxf(mx, y);
            neg += (int)(__float_as_uint(y) >> 31);
        }
    }
    if (rem) {
#pragma unroll
        for (int s = 0; s < K; s++) {
            if (s < rem) {
                unsigned ui = min((unsigned)ix, (unsigned)N_IN);
                z[(s + K - 1) % K] = xs[ui]; ix += d;
                float y = fmaf(w[0], z[s % K], bias);
#pragma unroll
                for (int t = 1; t < K; t++)
                    y = fmaf(w[t], z[(s + t) % K], y);
                mx = fmaxf(mx, y);
                neg += (int)(__float_as_uint(y) >> 31);
            }
        }
    }
}

template <int K>
__device__ __forceinline__ void conv_feat_dec(
    const float* __restrict__ xs,
    const float* __restrict__ wrow, float bias,
    int d, int p, int L,
    float& mx_out, int& neg_out)
{
    float w[K];
#pragma unroll
    for (int j = 0; j < K; j++) w[j] = wrow[j];

    float mx = -CUDART_INF_F;
    int   neg = 0;

    // Per-conv division results (2 divides total, amortized over all items):
    //   floor((p+r)/d) = pq + (prm + r >= d)   for r in [0,d)
    //   floor((A-r)/d) = aq  - (r > arm)       for r in [0,d), A >= 0
    const int A   = L - 1 - p;
    const int pq  = p / d, prm = p - pq * d;
    const int aq  = A / d, arm = A - aq * d;

    if (d >= TPB) {
        // one item per phase; full phase in one chunk
        for (int r = threadIdx.x; r < d; r += TPB) {
            const int m_lo = -(pq + ((prm + r) >= d ? 1 : 0));
            const int m_hi = aq - (r > arm ? 1 : 0);
            const int len  = m_hi - m_lo + 1;
            if (len <= 0) continue;
            const int i0 = r + m_lo * d;
            if (i0 >= 0 && i0 + (len + K - 2) * d < N_IN)
                ring_fast<K>(xs, w, bias, i0, d, len, mx, neg);
            else
                ring_clamped<K>(xs, w, bias, i0, d, len, mx, neg);
        }
    } else {
        const int maxlen = (L + d - 1) / d;
        const int nQ     = (maxlen + CHUNK - 1) / CHUNK;
        const int nItems = d * nQ;
        const float rd   = 1.0f / (float)d;

        for (int j = threadIdx.x; j < nItems; j += TPB) {
            // q = j / d, r = j % d via float reciprocal (+/-1 fixup)
            int q = (int)((float)j * rd);
            int r = j - q * d;
            if (r < 0)       { r += d; q--; }
            else if (r >= d) { r -= d; q++; }

            const int m_lo = -(pq + ((prm + r) >= d ? 1 : 0));
            const int m_hi = aq - (r > arm ? 1 : 0);
            const int m0   = m_lo + q * CHUNK;
            const int m1   = min(m0 + CHUNK, m_hi + 1);
            const int len  = m1 - m0;
            if (len <= 0) continue;
            const int i0 = r + m0 * d;
            if (i0 >= 0 && i0 + (len + K - 2) * d < N_IN)
                ring_fast<K>(xs, w, bias, i0, d, len, mx, neg);
            else
                ring_clamped<K>(xs, w, bias, i0, d, len, mx, neg);
        }
    }

    mx_out = mx;
    neg_out = neg;
}

__global__ void __launch_bounds__(TPB, 2)
feat_kernel(const float* __restrict__ x,
            const float* __restrict__ W,
            const float* __restrict__ B,
            const void* __restrict__ KS,
            const void* __restrict__ DS,
            const void* __restrict__ PS,
            float* __restrict__ out)
{
    extern __shared__ float xs[];   // N_IN + zero sentinel
    const int b = blockIdx.y;

    {
        const float4* xr4 = (const float4*)(x + (size_t)b * N_IN);
        float4* xs4 = (float4*)xs;
        for (int i = threadIdx.x; i < N_IN / 4; i += TPB)
            xs4[i] = xr4[i];
        if (threadIdx.x == 0) xs[N_IN] = 0.0f;
    }

    __shared__ float rmax[TPB / 32];
    __shared__ int   rneg[TPB / 32];
    __syncthreads();

    // int64 vs int32 metadata: kernel_sizes[0] in {7,9,11}; for int64 the
    // second 32-bit word is 0, for int32 it's kernel_sizes[1] (>=7).
    const bool is64 = (((const int*)KS)[1] == 0);

    const int c0 = blockIdx.x * CPB;
    for (int c = c0; c < c0 + CPB; ++c) {
        const int k = meta_at(KS, c, is64);
        const int d = meta_at(DS, c, is64);
        const int p = meta_at(PS, c, is64);
        const int L = N_IN + 2 * p - d * (k - 1);

        const float* wrow = W + c * KMAX;
        const float bias  = B[c];

        float mx; int neg;
        if (k == 7)       conv_feat_dec<7 >(xs, wrow, bias, d, p, L, mx, neg);
        else if (k == 9)  conv_feat_dec<9 >(xs, wrow, bias, d, p, L, mx, neg);
        else              conv_feat_dec<11>(xs, wrow, bias, d, p, L, mx, neg);

        mx  = warpReduceMax(mx);
        neg = warpReduceSum(neg);
        const int warp = threadIdx.x >> 5;
        const int lane = threadIdx.x & 31;
        if (lane == 0) { rmax[warp] = mx; rneg[warp] = neg; }
        __syncthreads();
        if (threadIdx.x == 0) {
            float m = rmax[0]; int n = rneg[0];
#pragma unroll
            for (int i = 1; i < TPB / 32; i++) {
                m = fmaxf(m, rmax[i]);
                n += rneg[i];
            }
            const size_t base = (size_t)b * (2 * NCONV) + 2 * c;
            out[base]     = m;
            out[base + 1] = (float)(L - n) / (float)L;
        }
        __syncthreads();
    }
}

extern "C" void kernel_launch(void* const* d_in, const int* in_sizes, int n_in,
                              void* d_out, int out_size)
{
    const float* x  = (const float*)d_in[0];
    const float* W  = (const float*)d_in[1];
    const float* B  = (const float*)d_in[2];
    const void*  KS = d_in[3];
    const void*  DS = d_in[4];
    const void*  PS = d_in[5];
    float* out = (float*)d_out;

    const int batch = in_sizes[0] / N_IN;   // 256

    const size_t smem = (N_IN + 16) * sizeof(float);
    cudaFuncSetAttribute(feat_kernel,
                         cudaFuncAttributeMaxDynamicSharedMemorySize,
                         (int)smem);

    dim3 grid(NCONV / CPB, batch);
    feat_kernel<<<grid, TPB, smem>>>(x, W, B, KS, DS, PS, out);
}

// round 15
// speedup vs baseline: 1.2290x; 1.0367x over previous
#include <cuda_runtime.h>
#include <math_constants.h>

#define N_IN   16384
#define NCONV  128
#define KMAX   11
#define TPB    256
#define CPB    16    // convs per block (processed block-cooperatively)
#define CHUNK  65    // 65 == 1 (mod 32) -> conflict-free lanes for any dilation

__device__ __forceinline__ float warpReduceMax(float v) {
#pragma unroll
    for (int o = 16; o > 0; o >>= 1)
        v = fmaxf(v, __shfl_xor_sync(0xffffffffu, v, o));
    return v;
}
__device__ __forceinline__ int warpReduceSum(int v) {
#pragma unroll
    for (int o = 16; o > 0; o >>= 1)
        v += __shfl_xor_sync(0xffffffffu, v, o);
    return v;
}

__device__ __forceinline__ int meta_at(const void* arr, int c, bool is64) {
    if (is64) return (int)((const long long*)arr)[c];
    return ((const int*)arr)[c];
}

// Dual-chain dot product over the ring window for output slot s (compile-time).
// Two independent FMA chains halve the dependency critical path; +1 FADD.
template <int K>
__device__ __forceinline__ float dot2_ring(
    const float* __restrict__ w, const float (&z)[K], float bias, int s)
{
    float y0 = fmaf(w[0], z[s % K], bias);
    float y1 = w[1] * z[(s + 1) % K];
#pragma unroll
    for (int t = 2; t < K; t++) {
        if (t & 1) y1 = fmaf(w[t], z[(s + t) % K], y1);
        else       y0 = fmaf(w[t], z[(s + t) % K], y0);
    }
    return y0 + y1;
}

// Dual-chain dot for the tail: taps are z[0..K-2] (oldest first) then nw.
template <int K>
__device__ __forceinline__ float dot2_tail(
    const float* __restrict__ w, const float (&z)[K], float nw, float bias)
{
    float y0 = fmaf(w[0], z[0], bias);
    float y1 = w[1] * z[1];
#pragma unroll
    for (int t = 2; t < K; t++) {
        float tap = (t < K - 1) ? z[t] : nw;
        if (t & 1) y1 = fmaf(w[t], tap, y1);
        else       y0 = fmaf(w[t], tap, y0);
    }
    return y0 + y1;
}

// ---- ring FIR, no bounds checks. Loads exactly len+K-1 taps:
// preload K-1, then load-one/compute-one. Max address: i0+(len+K-2)*d. ----
template <int K>
__device__ __forceinline__ void ring_fast(
    const float* __restrict__ xs, const float* __restrict__ w, float bias,
    int i0, int d, int len, float& mx, int& neg)
{
    const float* ptr = xs + i0;
    float z[K];
#pragma unroll
    for (int s = 0; s < K - 1; s++) { z[s] = *ptr; ptr += d; }

    const int full = len / K;
    const int rem  = len - full * K;

    for (int g = 0; g < full; g++) {
#pragma unroll
        for (int s = 0; s < K; s++) {
            z[(s + K - 1) % K] = *ptr; ptr += d;   // newest tap
            float y = dot2_ring<K>(w, z, bias, s);
            mx = fmaxf(mx, y);
            neg += (int)(__float_as_uint(y) >> 31);
        }
    }
    // exact-length tail: after full groups, z[0..K-2] hold the K-1 history
    // taps oldest-first (tap index == slot mod K; full*K == 0 mod K).
#pragma unroll 1
    for (int s = 0; s < rem; s++) {
        float nw = *ptr; ptr += d;
        float y = dot2_tail<K>(w, z, nw, bias);
        mx = fmaxf(mx, y);
        neg += (int)(__float_as_uint(y) >> 31);
#pragma unroll
        for (int t = 0; t < K - 2; t++) z[t] = z[t + 1];
        z[K - 2] = nw;
    }
}

// ---- same ring, OOB taps clamped to zero sentinel xs[N_IN] (edge chunks) ----
template <int K>
__device__ __forceinline__ void ring_clamped(
    const float* __restrict__ xs, const float* __restrict__ w, float bias,
    int i0, int d, int len, float& mx, int& neg)
{
    int ix = i0;
    float z[K];
#pragma unroll
    for (int s = 0; s < K - 1; s++) {
        unsigned ui = min((unsigned)ix, (unsigned)N_IN);
        z[s] = xs[ui]; ix += d;
    }

    const int full = len / K;
    const int rem  = len - full * K;

    for (int g = 0; g < full; g++) {
#pragma unroll
        for (int s = 0; s < K; s++) {
            unsigned ui = min((unsigned)ix, (unsigned)N_IN);
            z[(s + K - 1) % K] = xs[ui]; ix += d;
            float y = dot2_ring<K>(w, z, bias, s);
            mx = fmaxf(mx, y);
            neg += (int)(__float_as_uint(y) >> 31);
        }
    }
#pragma unroll 1
    for (int s = 0; s < rem; s++) {
        unsigned ui = min((unsigned)ix, (unsigned)N_IN);
        float nw = xs[ui]; ix += d;
        float y = dot2_tail<K>(w, z, nw, bias);
        mx = fmaxf(mx, y);
        neg += (int)(__float_as_uint(y) >> 31);
#pragma unroll
        for (int t = 0; t < K - 2; t++) z[t] = z[t + 1];
        z[K - 2] = nw;
    }
}

template <int K>
__device__ __forceinline__ void conv_feat_dec(
    const float* __restrict__ xs,
    const float* __restrict__ wrow, float bias,
    int d, int p, int L,
    float& mx_out, int& neg_out)
{
    float w[K];
#pragma unroll
    for (int j = 0; j < K; j++) w[j] = wrow[j];

    float mx = -CUDART_INF_F;
    int   neg = 0;

    // Per-conv division results (2 divides total, amortized over all items):
    //   floor((p+r)/d) = pq + (prm + r >= d)   for r in [0,d)
    //   floor((A-r)/d) = aq  - (r > arm)       for r in [0,d), A >= 0
    const int A   = L - 1 - p;
    const int pq  = p / d, prm = p - pq * d;
    const int aq  = A / d, arm = A - aq * d;

    if (d >= TPB) {
        // one item per phase; full phase in one chunk
        for (int r = threadIdx.x; r < d; r += TPB) {
            const int m_lo = -(pq + ((prm + r) >= d ? 1 : 0));
            const int m_hi = aq - (r > arm ? 1 : 0);
            const int len  = m_hi - m_lo + 1;
            if (len <= 0) continue;
            const int i0 = r + m_lo * d;
            if (i0 >= 0 && i0 + (len + K - 2) * d < N_IN)
                ring_fast<K>(xs, w, bias, i0, d, len, mx, neg);
            else
                ring_clamped<K>(xs, w, bias, i0, d, len, mx, neg);
        }
    } else {
        const int maxlen = (L + d - 1) / d;
        const int nQ     = (maxlen + CHUNK - 1) / CHUNK;
        const int nItems = d * nQ;
        const float rd   = 1.0f / (float)d;

        for (int j = threadIdx.x; j < nItems; j += TPB) {
            // q = j / d, r = j % d via float reciprocal (+/-1 fixup)
            int q = (int)((float)j * rd);
            int r = j - q * d;
            if (r < 0)       { r += d; q--; }
            else if (r >= d) { r -= d; q++; }

            const int m_lo = -(pq + ((prm + r) >= d ? 1 : 0));
            const int m_hi = aq - (r > arm ? 1 : 0);
            const int m0   = m_lo + q * CHUNK;
            const int m1   = min(m0 + CHUNK, m_hi + 1);
            const int len  = m1 - m0;
            if (len <= 0) continue;
            const int i0 = r + m0 * d;
            if (i0 >= 0 && i0 + (len + K - 2) * d < N_IN)
                ring_fast<K>(xs, w, bias, i0, d, len, mx, neg);
            else
                ring_clamped<K>(xs, w, bias, i0, d, len, mx, neg);
        }
    }

    mx_out = mx;
    neg_out = neg;
}

__global__ void __launch_bounds__(TPB, 3)
feat_kernel(const float* __restrict__ x,
            const float* __restrict__ W,
            const float* __restrict__ B,
            const void* __restrict__ KS,
            const void* __restrict__ DS,
            const void* __restrict__ PS,
            float* __restrict__ out)
{
    extern __shared__ float xs[];   // N_IN + zero sentinel
    const int b = blockIdx.y;

    {
        const float4* xr4 = (const float4*)(x + (size_t)b * N_IN);
        float4* xs4 = (float4*)xs;
        for (int i = threadIdx.x; i < N_IN / 4; i += TPB)
            xs4[i] = xr4[i];
        if (threadIdx.x == 0) xs[N_IN] = 0.0f;
    }

    __shared__ float rmax[TPB / 32];
    __shared__ int   rneg[TPB / 32];
    __syncthreads();

    // int64 vs int32 metadata: kernel_sizes[0] in {7,9,11}; for int64 the
    // second 32-bit word is 0, for int32 it's kernel_sizes[1] (>=7).
    const bool is64 = (((const int*)KS)[1] == 0);

    const int c0 = blockIdx.x * CPB;
    for (int c = c0; c < c0 + CPB; ++c) {
        const int k = meta_at(KS, c, is64);
        const int d = meta_at(DS, c, is64);
        const int p = meta_at(PS, c, is64);
        const int L = N_IN + 2 * p - d * (k - 1);

        const float* wrow = W + c * KMAX;
        const float bias  = B[c];

        float mx; int neg;
        if (k == 7)       conv_feat_dec<7 >(xs, wrow, bias, d, p, L, mx, neg);
        else if (k == 9)  conv_feat_dec<9 >(xs, wrow, bias, d, p, L, mx, neg);
        else              conv_feat_dec<11>(xs, wrow, bias, d, p, L, mx, neg);

        mx  = warpReduceMax(mx);
        neg = warpReduceSum(neg);
        const int warp = threadIdx.x >> 5;
        const int lane = threadIdx.x & 31;
        if (lane == 0) { rmax[warp] = mx; rneg[warp] = neg; }
        __syncthreads();
        if (threadIdx.x == 0) {
            float m = rmax[0]; int n = rneg[0];
#pragma unroll
            for (int i = 1; i < TPB / 32; i++) {
                m = fmaxf(m, rmax[i]);
                n += rneg[i];
            }
            const size_t base = (size_t)b * (2 * NCONV) + 2 * c;
            out[base]     = m;
            out[base + 1] = (float)(L - n) / (float)L;
        }
        __syncthreads();
    }
}

extern "C" void kernel_launch(void* const* d_in, const int* in_sizes, int n_in,
                              void* d_out, int out_size)
{
    const float* x  = (const float*)d_in[0];
    const float* W  = (const float*)d_in[1];
    const float* B  = (const float*)d_in[2];
    const void*  KS = d_in[3];
    const void*  DS = d_in[4];
    const void*  PS = d_in[5];
    float* out = (float*)d_out;

    const int batch = in_sizes[0] / N_IN;   // 256

    const size_t smem = (N_IN + 16) * sizeof(float);
    cudaFuncSetAttribute(feat_kernel,
                         cudaFuncAttributeMaxDynamicSharedMemorySize,
                         (int)smem);

    dim3 grid(NCONV / CPB, batch);
    feat_kernel<<<grid, TPB, smem>>>(x, W, B, KS, DS, PS, out);
}